// round 12
// baseline (speedup 1.0000x reference)
#include <cuda_runtime.h>
#include <math.h>
#include <stdint.h>

// Problem constants
#define B_  2
#define T_  2048
#define C_  1024
#define H_  16
#define D_  64
#define BH_ (B_ * H_)       // 32
#define M_  (B_ * T_)       // 4096

// Scratch (device globals — no allocation allowed)
__device__ float g_q[BH_ * T_ * D_];     // [bh][t][d]
__device__ float g_k[BH_ * T_ * D_];
__device__ float g_v[BH_ * T_ * D_];
__device__ float g_ctx[M_ * C_];         // [b*t][h*64+d]

// ===========================================================================
// tf32 warp MMA helpers (sm_80+ baseline — valid on plain sm_103 target)
// ===========================================================================
__device__ __forceinline__ uint32_t f2tf32(float f) {
    uint32_t u;
    asm("cvt.rna.tf32.f32 %0, %1;" : "=r"(u) : "f"(f));
    return u;
}

__device__ __forceinline__ void mma_tf32(float* c, const uint32_t* a,
                                         const uint32_t* b) {
    asm volatile(
        "mma.sync.aligned.m16n8k8.row.col.f32.tf32.tf32.f32 "
        "{%0,%1,%2,%3}, {%4,%5,%6,%7}, {%8,%9}, {%0,%1,%2,%3};"
        : "+f"(c[0]), "+f"(c[1]), "+f"(c[2]), "+f"(c[3])
        : "r"(a[0]), "r"(a[1]), "r"(a[2]), "r"(a[3]), "r"(b[0]), "r"(b[1]));
}

// ===========================================================================
// tf32 mma.sync GEMM, software-pipelined (UNDER TEST this round):
// CTA 128x128, 8 warps, warp 64x32, K-stage 32, double-buffered smem.
// Per stage: sync; LDG(next)->regs; MMA(cur buf); STS(regs)->next buf.
// Bank layouts identical to R10 (APAD 36 / BPAD 136); buffer bases are
// multiples of 32 words so the verified patterns are preserved.
// ===========================================================================
#define APAD 36
#define BPAD 136
#define GEMM_SMEM_WORDS (2 * 128 * APAD + 2 * 32 * BPAD)
#define GEMM_SMEM_BYTES (GEMM_SMEM_WORDS * 4)   // 71680

template <int MODE>
__global__ __launch_bounds__(256, 2) void mma_gemm(const float* __restrict__ Ain,
                                                   const float* __restrict__ Bw,
                                                   const float* __restrict__ bias,
                                                   float* __restrict__ Out,
                                                   int N) {
    extern __shared__ uint32_t smg[];
    uint32_t* const As0 = smg;
    uint32_t* const As1 = smg + 128 * APAD;
    uint32_t* const Bs0 = smg + 2 * 128 * APAD;
    uint32_t* const Bs1 = smg + 2 * 128 * APAD + 32 * BPAD;

    const int tid = threadIdx.x;
    const int wid = tid >> 5, lane = tid & 31;
    const int warp_m = (wid >> 2) * 64;
    const int warp_n = (wid & 3) * 32;
    const int g = lane >> 2, t = lane & 3;
    const int bm = blockIdx.y * 128, bn = blockIdx.x * 128;

    const float* Ap = (MODE == 0) ? Ain : (const float*)g_ctx;

    float acc[4][4][4];
#pragma unroll
    for (int mf = 0; mf < 4; mf++)
#pragma unroll
        for (int nf = 0; nf < 4; nf++)
#pragma unroll
            for (int r = 0; r < 4; r++) acc[mf][nf][r] = 0.f;

    float4 aR[4], bR[4];
    // Prologue: load stage 0 and store into buf 0.
#pragma unroll
    for (int r = 0; r < 4; r++) {
        int idx = tid + r * 256;
        int m = idx >> 3, kk = idx & 7;
        aR[r] = *(const float4*)(Ap + (size_t)(bm + m) * C_ + kk * 4);
        int k = idx >> 5, n4 = idx & 31;
        bR[r] = *(const float4*)(Bw + (size_t)k * N + bn + n4 * 4);
    }
#pragma unroll
    for (int r = 0; r < 4; r++) {
        int idx = tid + r * 256;
        int m = idx >> 3, kk = idx & 7;
        uint32_t* d = &As0[m * APAD + kk * 4];
        d[0] = f2tf32(aR[r].x); d[1] = f2tf32(aR[r].y);
        d[2] = f2tf32(aR[r].z); d[3] = f2tf32(aR[r].w);
        int k = idx >> 5, n4 = idx & 31;
        uint32_t* e = &Bs0[k * BPAD + n4 * 4];
        e[0] = f2tf32(bR[r].x); e[1] = f2tf32(bR[r].y);
        e[2] = f2tf32(bR[r].z); e[3] = f2tf32(bR[r].w);
    }

    for (int s = 0; s < 32; s++) {
        __syncthreads();   // buf[s&1] visible; reads of other buf (s-1) done
        const uint32_t* As = (s & 1) ? As1 : As0;
        const uint32_t* Bs = (s & 1) ? Bs1 : Bs0;

        if (s < 31) {      // prefetch stage s+1 into regs
            const int k0 = (s + 1) * 32;
#pragma unroll
            for (int r = 0; r < 4; r++) {
                int idx = tid + r * 256;
                int m = idx >> 3, kk = idx & 7;
                aR[r] = *(const float4*)(Ap + (size_t)(bm + m) * C_ + k0 + kk * 4);
                int k = idx >> 5, n4 = idx & 31;
                bR[r] = *(const float4*)(Bw + (size_t)(k0 + k) * N + bn + n4 * 4);
            }
        }

#pragma unroll
        for (int ks = 0; ks < 4; ks++) {
            const int kb = ks * 8;
            uint32_t af[4][4], bf[4][2];
#pragma unroll
            for (int mf = 0; mf < 4; mf++) {
                const uint32_t* ap = &As[(warp_m + mf * 16 + g) * APAD + kb + t];
                af[mf][0] = ap[0];
                af[mf][1] = ap[8 * APAD];
                af[mf][2] = ap[4];
                af[mf][3] = ap[8 * APAD + 4];
            }
#pragma unroll
            for (int nf = 0; nf < 4; nf++) {
                const uint32_t* bp = &Bs[(kb + t) * BPAD + warp_n + nf * 8 + g];
                bf[nf][0] = bp[0];
                bf[nf][1] = bp[4 * BPAD];
            }
#pragma unroll
            for (int mf = 0; mf < 4; mf++)
#pragma unroll
                for (int nf = 0; nf < 4; nf++)
                    mma_tf32(acc[mf][nf], af[mf], bf[nf]);
        }

        if (s < 31) {      // stash prefetched stage into the other buffer
            uint32_t* An = (s & 1) ? As0 : As1;
            uint32_t* Bn = (s & 1) ? Bs0 : Bs1;
#pragma unroll
            for (int r = 0; r < 4; r++) {
                int idx = tid + r * 256;
                int m = idx >> 3, kk = idx & 7;
                uint32_t* d = &An[m * APAD + kk * 4];
                d[0] = f2tf32(aR[r].x); d[1] = f2tf32(aR[r].y);
                d[2] = f2tf32(aR[r].z); d[3] = f2tf32(aR[r].w);
                int k = idx >> 5, n4 = idx & 31;
                uint32_t* e = &Bn[k * BPAD + n4 * 4];
                e[0] = f2tf32(bR[r].x); e[1] = f2tf32(bR[r].y);
                e[2] = f2tf32(bR[r].z); e[3] = f2tf32(bR[r].w);
            }
        }
    }

#pragma unroll
    for (int mf = 0; mf < 4; mf++) {
#pragma unroll
        for (int nf = 0; nf < 4; nf++) {
            const int n = bn + warp_n + nf * 8 + 2 * t;
            const float b0v = bias[n], b1v = bias[n + 1];
#pragma unroll
            for (int half = 0; half < 2; half++) {
                const int m = bm + warp_m + mf * 16 + g + half * 8;
                float v0 = acc[mf][nf][half * 2 + 0] + b0v;
                float v1 = acc[mf][nf][half * 2 + 1] + b1v;
                if (MODE == 0) {
                    int which = n >> 10;
                    int rem = n & 1023;
                    int h = rem >> 6, d = rem & 63;
                    int bi = m >> 11, tt = m & (T_ - 1);
                    float* dst = (which == 0) ? g_q : (which == 1) ? g_k : g_v;
                    *(float2*)&dst[(size_t)(((bi << 4) + h) * T_ + tt) * D_ + d] =
                        make_float2(v0, v1);
                } else {
                    *(float2*)&Out[(size_t)m * N + n] = make_float2(v0, v1);
                }
            }
        }
    }
}

// ===========================================================================
// tf32 mma.sync flash attention — EXACT R10 version (proven correct/passing).
// Single-buffered K/V, two syncs per tile.
// ===========================================================================
#define QK_PAD 68
#define V_PAD  72
#define ATTN_SMEM_BYTES ((128 * QK_PAD + 64 * QK_PAD + 64 * V_PAD) * 4)

__global__ __launch_bounds__(256, 2) void attn_mma() {
    extern __shared__ uint32_t smu[];
    uint32_t* Qs = smu;                               // [128][68]
    uint32_t* Ks = smu + 128 * QK_PAD;                // [64][68]
    uint32_t* Vs = smu + 128 * QK_PAD + 64 * QK_PAD;  // [64][72]

    const int tid = threadIdx.x;
    const int wid = tid >> 5, lane = tid & 31;
    const int g = lane >> 2, t = lane & 3;
    const int bh = blockIdx.y;
    const int q0 = blockIdx.x * 128;
    const int qrow = wid * 16;

    const float* Qg = g_q + (size_t)bh * T_ * D_;
    const float* Kg = g_k + (size_t)bh * T_ * D_;
    const float* Vg = g_v + (size_t)bh * T_ * D_;

    // Load Q tile (scaled by 1/8, tf32). 128x64 floats, coalesced LDG.128.
#pragma unroll
    for (int r = 0; r < 8; r++) {
        int idx = tid + r * 256;
        int m = idx >> 4, c4 = idx & 15;
        float4 v = *(const float4*)(Qg + (size_t)(q0 + m) * D_ + c4 * 4);
        *(uint4*)&Qs[m * QK_PAD + c4 * 4] =
            make_uint4(f2tf32(v.x * 0.125f), f2tf32(v.y * 0.125f),
                       f2tf32(v.z * 0.125f), f2tf32(v.w * 0.125f));
    }

    float m_i[2] = {-1e30f, -1e30f};
    float l_i[2] = {0.f, 0.f};
    float o[8][4];
#pragma unroll
    for (int nb = 0; nb < 8; nb++)
#pragma unroll
        for (int r = 0; r < 4; r++) o[nb][r] = 0.f;

    for (int kt = 0; kt < T_; kt += 64) {
        __syncthreads();   // prior tile consumed (and Q stores on iter 0)

        // Load K,V tiles 64x64 each (tf32).
#pragma unroll
        for (int r = 0; r < 4; r++) {
            int idx = tid + r * 256;
            int s = idx >> 4, c4 = idx & 15;
            float4 v = *(const float4*)(Kg + (size_t)(kt + s) * D_ + c4 * 4);
            *(uint4*)&Ks[s * QK_PAD + c4 * 4] =
                make_uint4(f2tf32(v.x), f2tf32(v.y), f2tf32(v.z), f2tf32(v.w));
        }
#pragma unroll
        for (int r = 0; r < 4; r++) {
            int idx = tid + r * 256;
            int s = idx >> 4, c4 = idx & 15;
            float4 v = *(const float4*)(Vg + (size_t)(kt + s) * D_ + c4 * 4);
            *(uint4*)&Vs[s * V_PAD + c4 * 4] =
                make_uint4(f2tf32(v.x), f2tf32(v.y), f2tf32(v.z), f2tf32(v.w));
        }
        __syncthreads();

        // S = (Q/8) @ K^T
        float sfr[8][4];
#pragma unroll
        for (int nb = 0; nb < 8; nb++)
#pragma unroll
            for (int r = 0; r < 4; r++) sfr[nb][r] = 0.f;

#pragma unroll
        for (int ks = 0; ks < 8; ks++) {
            uint32_t af[4];
            const uint32_t* ap = &Qs[(qrow + g) * QK_PAD + ks * 8 + t];
            af[0] = ap[0];
            af[1] = ap[8 * QK_PAD];
            af[2] = ap[4];
            af[3] = ap[8 * QK_PAD + 4];
#pragma unroll
            for (int nb = 0; nb < 8; nb++) {
                uint32_t bf[2];
                const uint32_t* bp = &Ks[(nb * 8 + g) * QK_PAD + ks * 8 + t];
                bf[0] = bp[0];
                bf[1] = bp[4];
                mma_tf32(sfr[nb], af, bf);
            }
        }

        // Online softmax per row-half (rows g, g+8), in-place exp on sfr.
#pragma unroll
        for (int half = 0; half < 2; half++) {
            const int h2 = half * 2;
            float mx = sfr[0][h2];
#pragma unroll
            for (int nb = 0; nb < 8; nb++) {
                mx = fmaxf(mx, sfr[nb][h2]);
                mx = fmaxf(mx, sfr[nb][h2 + 1]);
            }
            mx = fmaxf(mx, __shfl_xor_sync(0xffffffffu, mx, 1));
            mx = fmaxf(mx, __shfl_xor_sync(0xffffffffu, mx, 2));
            float mnew = fmaxf(m_i[half], mx);
            float corr = __expf(m_i[half] - mnew);
            m_i[half] = mnew;
            float ps = 0.f;
#pragma unroll
            for (int nb = 0; nb < 8; nb++) {
                float p0 = __expf(sfr[nb][h2] - mnew);
                float p1 = __expf(sfr[nb][h2 + 1] - mnew);
                sfr[nb][h2] = p0;
                sfr[nb][h2 + 1] = p1;
                ps += p0 + p1;
            }
            ps += __shfl_xor_sync(0xffffffffu, ps, 1);
            ps += __shfl_xor_sync(0xffffffffu, ps, 2);
            l_i[half] = l_i[half] * corr + ps;
#pragma unroll
            for (int nb = 0; nb < 8; nb++) {
                o[nb][h2] *= corr;
                o[nb][h2 + 1] *= corr;
            }
        }

        // O += P @ V
        const int src0 = (lane & ~3) | (t >> 1);
#pragma unroll
        for (int ks = 0; ks < 8; ks++) {
            float x00 = __shfl_sync(0xffffffffu, sfr[ks][0], src0);
            float x01 = __shfl_sync(0xffffffffu, sfr[ks][1], src0);
            float x20 = __shfl_sync(0xffffffffu, sfr[ks][0], src0 + 2);
            float x21 = __shfl_sync(0xffffffffu, sfr[ks][1], src0 + 2);
            float x10 = __shfl_sync(0xffffffffu, sfr[ks][2], src0);
            float x11 = __shfl_sync(0xffffffffu, sfr[ks][3], src0);
            float x30 = __shfl_sync(0xffffffffu, sfr[ks][2], src0 + 2);
            float x31 = __shfl_sync(0xffffffffu, sfr[ks][3], src0 + 2);
            uint32_t af[4];
            af[0] = f2tf32((t & 1) ? x01 : x00);
            af[1] = f2tf32((t & 1) ? x11 : x10);
            af[2] = f2tf32((t & 1) ? x21 : x20);
            af[3] = f2tf32((t & 1) ? x31 : x30);
#pragma unroll
            for (int db = 0; db < 8; db++) {
                uint32_t bf[2];
                const uint32_t* bp = &Vs[(ks * 8 + t) * V_PAD + db * 8 + g];
                bf[0] = bp[0];
                bf[1] = bp[4 * V_PAD];
                mma_tf32(o[db], af, bf);
            }
        }
    }

    // Normalize and write ctx[b][t][h*64+d]
    const int bi = bh >> 4, h = bh & 15;
    const float inv0 = 1.0f / l_i[0];
    const float inv1 = 1.0f / l_i[1];
#pragma unroll
    for (int db = 0; db < 8; db++) {
        const int d = db * 8 + 2 * t;
#pragma unroll
        for (int half = 0; half < 2; half++) {
            const float inv = half ? inv1 : inv0;
            const int tq = q0 + qrow + g + half * 8;
            float* dst = g_ctx + (size_t)(bi * T_ + tq) * C_ + h * D_ + d;
            *(float2*)dst = make_float2(o[db][half * 2] * inv,
                                        o[db][half * 2 + 1] * inv);
        }
    }
}

// ---------------------------------------------------------------------------
// Launch
// ---------------------------------------------------------------------------
extern "C" void kernel_launch(void* const* d_in, const int* in_sizes, int n_in,
                              void* d_out, int out_size) {
    const float* x     = (const float*)d_in[0];
    const float* W_qkv = (const float*)d_in[1];
    const float* b_qkv = (const float*)d_in[2];
    const float* W_out = (const float*)d_in[3];
    const float* b_out = (const float*)d_in[4];
    float* out = (float*)d_out;

    (void)in_sizes; (void)n_in; (void)out_size;

    cudaFuncSetAttribute(mma_gemm<0>, cudaFuncAttributeMaxDynamicSharedMemorySize,
                         GEMM_SMEM_BYTES);
    cudaFuncSetAttribute(mma_gemm<1>, cudaFuncAttributeMaxDynamicSharedMemorySize,
                         GEMM_SMEM_BYTES);
    cudaFuncSetAttribute(attn_mma, cudaFuncAttributeMaxDynamicSharedMemorySize,
                         ATTN_SMEM_BYTES);

    mma_gemm<0><<<dim3(3 * C_ / 128, M_ / 128), 256, GEMM_SMEM_BYTES>>>(
        x, W_qkv, b_qkv, nullptr, 3 * C_);
    attn_mma<<<dim3(T_ / 128, BH_), 256, ATTN_SMEM_BYTES>>>();
    mma_gemm<1><<<dim3(C_ / 128, M_ / 128), 256, GEMM_SMEM_BYTES>>>(
        nullptr, W_out, b_out, out, C_);
}